// round 2
// baseline (speedup 1.0000x reference)
#include <cuda_runtime.h>

// Fixed problem shape (from reference): N = 100,000 nodes.
#define MAX_NODES 100000

// Scratch: degree accumulators, later overwritten in-place with rsqrt(deg).
__device__ float g_outdeg[MAX_NODES];
__device__ float g_indeg[MAX_NODES];

// ---------------------------------------------------------------------------
// Kernel 1: zero the accumulators (device globals persist across graph
// replays, so they MUST be re-zeroed on every launch).
// ---------------------------------------------------------------------------
__global__ void zero_deg_kernel() {
    int i = blockIdx.x * blockDim.x + threadIdx.x;
    if (i < MAX_NODES) {
        g_outdeg[i] = 0.0f;
        g_indeg[i]  = 0.0f;
    }
}

// ---------------------------------------------------------------------------
// Kernel 2: scatter edge weights into out-degree (by src) and in-degree (by
// dst). Streaming loads use __ldcs (evict-first) — the atomics bypass L1, so
// keep L1 clean. Bound by REDG issue rate (1.29 cyc/lane/SM), near floor.
// ---------------------------------------------------------------------------
__global__ void scatter_deg_kernel(const float4* __restrict__ w4,
                                   const int4*   __restrict__ s4,
                                   const int4*   __restrict__ d4,
                                   const float*  __restrict__ w,
                                   const int*    __restrict__ s,
                                   const int*    __restrict__ d,
                                   int n4, int E) {
    int tid = blockIdx.x * blockDim.x + threadIdx.x;
    if (tid < n4) {
        float4 wv = __ldcs(&w4[tid]);
        int4   sv = __ldcs(&s4[tid]);
        int4   dv = __ldcs(&d4[tid]);
        atomicAdd(&g_outdeg[sv.x], wv.x);
        atomicAdd(&g_outdeg[sv.y], wv.y);
        atomicAdd(&g_outdeg[sv.z], wv.z);
        atomicAdd(&g_outdeg[sv.w], wv.w);
        atomicAdd(&g_indeg[dv.x], wv.x);
        atomicAdd(&g_indeg[dv.y], wv.y);
        atomicAdd(&g_indeg[dv.z], wv.z);
        atomicAdd(&g_indeg[dv.w], wv.w);
    } else {
        int i = 4 * n4 + (tid - n4);
        if (i < E) {
            float wv = __ldcs(&w[i]);
            atomicAdd(&g_outdeg[__ldcs(&s[i])], wv);
            atomicAdd(&g_indeg[__ldcs(&d[i])], wv);
        }
    }
}

// ---------------------------------------------------------------------------
// Kernel 3: per-node rsqrt, in place. deg==0 -> +inf, but such nodes never
// appear on the corresponding side of any edge, so the inf is never gathered.
// ---------------------------------------------------------------------------
__global__ void rsqrt_deg_kernel(const int* __restrict__ num_nodes) {
    int n = *num_nodes;
    int i = blockIdx.x * blockDim.x + threadIdx.x;
    if (i < n) {
        g_outdeg[i] = rsqrtf(g_outdeg[i]);
        g_indeg[i]  = rsqrtf(g_indeg[i]);
    }
}

// ---------------------------------------------------------------------------
// Kernel 4: per-edge gather-multiply.
//  - Streaming inputs/output use __ldcs/__stcs (evict-first) so L1 is
//    reserved for the 800KB norm tables -> ~28% of random gathers hit L1
//    instead of burning 32B L2 sectors each.
//  - Two float4 groups per thread: 8 edges, 22 loads in flight -> high MLP.
// ---------------------------------------------------------------------------
__global__ void gather_mul_kernel(const float4* __restrict__ w4,
                                  const int4*   __restrict__ s4,
                                  const int4*   __restrict__ d4,
                                  const float*  __restrict__ w,
                                  const int*    __restrict__ s,
                                  const int*    __restrict__ d,
                                  float4* __restrict__ out4,
                                  float*  __restrict__ out,
                                  int n4, int E) {
    int tid = blockIdx.x * blockDim.x + threadIdx.x;
    int nthreads8 = (n4 + 1) / 2;  // threads handling pairs of float4 groups
    if (tid < nthreads8) {
        int i0 = 2 * tid;
        int i1 = 2 * tid + 1;
        // Batch all streaming loads first (front-batched LDG -> deep MLP)
        float4 wv0 = __ldcs(&w4[i0]);
        int4   sv0 = __ldcs(&s4[i0]);
        int4   dv0 = __ldcs(&d4[i0]);
        bool has1 = (i1 < n4);
        float4 wv1 = has1 ? __ldcs(&w4[i1]) : make_float4(0, 0, 0, 0);
        int4   sv1 = has1 ? __ldcs(&s4[i1]) : make_int4(0, 0, 0, 0);
        int4   dv1 = has1 ? __ldcs(&d4[i1]) : make_int4(0, 0, 0, 0);

        // Gather all 16 norms (default caching path -> L1-resident tables)
        float so0x = __ldg(&g_outdeg[sv0.x]), so0y = __ldg(&g_outdeg[sv0.y]);
        float so0z = __ldg(&g_outdeg[sv0.z]), so0w = __ldg(&g_outdeg[sv0.w]);
        float di0x = __ldg(&g_indeg[dv0.x]),  di0y = __ldg(&g_indeg[dv0.y]);
        float di0z = __ldg(&g_indeg[dv0.z]),  di0w = __ldg(&g_indeg[dv0.w]);

        float4 r0;
        r0.x = so0x * di0x * wv0.x;
        r0.y = so0y * di0y * wv0.y;
        r0.z = so0z * di0z * wv0.z;
        r0.w = so0w * di0w * wv0.w;
        __stcs(&out4[i0], r0);

        if (has1) {
            float so1x = __ldg(&g_outdeg[sv1.x]), so1y = __ldg(&g_outdeg[sv1.y]);
            float so1z = __ldg(&g_outdeg[sv1.z]), so1w = __ldg(&g_outdeg[sv1.w]);
            float di1x = __ldg(&g_indeg[dv1.x]),  di1y = __ldg(&g_indeg[dv1.y]);
            float di1z = __ldg(&g_indeg[dv1.z]),  di1w = __ldg(&g_indeg[dv1.w]);
            float4 r1;
            r1.x = so1x * di1x * wv1.x;
            r1.y = so1y * di1y * wv1.y;
            r1.z = so1z * di1z * wv1.z;
            r1.w = so1w * di1w * wv1.w;
            __stcs(&out4[i1], r1);
        }
    } else {
        int i = 4 * n4 + (tid - nthreads8);
        if (i < E) {
            out[i] = __ldg(&g_outdeg[__ldcs(&s[i])]) *
                     __ldg(&g_indeg[__ldcs(&d[i])]) * __ldcs(&w[i]);
        }
    }
}

extern "C" void kernel_launch(void* const* d_in, const int* in_sizes, int n_in,
                              void* d_out, int out_size) {
    const float* w   = (const float*)d_in[0];
    const int*   src = (const int*)d_in[1];
    const int*   dst = (const int*)d_in[2];
    const int*   nn  = (const int*)d_in[3];  // num_nodes (device scalar)
    float* out = (float*)d_out;

    int E  = in_sizes[0];
    int n4 = E / 4;
    int tail = E - 4 * n4;

    const int TPB = 256;

    zero_deg_kernel<<<(MAX_NODES + TPB - 1) / TPB, TPB>>>();

    int nthreads_sc = n4 + tail;
    scatter_deg_kernel<<<(nthreads_sc + TPB - 1) / TPB, TPB>>>(
        (const float4*)w, (const int4*)src, (const int4*)dst,
        w, src, dst, n4, E);

    rsqrt_deg_kernel<<<(MAX_NODES + TPB - 1) / TPB, TPB>>>(nn);

    int nthreads_g = (n4 + 1) / 2 + tail;
    gather_mul_kernel<<<(nthreads_g + TPB - 1) / TPB, TPB>>>(
        (const float4*)w, (const int4*)src, (const int4*)dst,
        w, src, dst, (float4*)out, out, n4, E);
}

// round 3
// speedup vs baseline: 1.0665x; 1.0665x over previous
#include <cuda_runtime.h>

// Fixed problem shape (from reference): N = 100,000 nodes.
#define MAX_NODES 100000

// Combined scratch table: [0, N) = out-degree (by src), [N, 2N) = in-degree
// (by dst). Later overwritten in-place with rsqrt(deg).
__device__ float g_norm[2 * MAX_NODES];

// ---------------------------------------------------------------------------
// Kernel 1: zero the accumulators, float4-vectorized (2N = 200,000 floats ->
// 50,000 float4 stores). Device globals persist across graph replays, so they
// MUST be re-zeroed on every launch.
// ---------------------------------------------------------------------------
__global__ void zero_deg_kernel() {
    int i = blockIdx.x * blockDim.x + threadIdx.x;
    if (i < (2 * MAX_NODES) / 4) {
        ((float4*)g_norm)[i] = make_float4(0.f, 0.f, 0.f, 0.f);
    }
}

// ---------------------------------------------------------------------------
// Kernel 2: scatter edge weights into out-degree (by src) and in-degree (by
// dst). 4 edges per thread via float4/int4 loads; NO tail branch (E % 4 == 0
// for this problem; remainder handled by a tiny separate kernel if ever
// nonzero). atomicAdd with unused return -> REDG (no round trip).
// Bound by spread-addr REDG rate (~1.3 cyc/lane/SM) -> ~250us floor.
// ---------------------------------------------------------------------------
__global__ void scatter_deg_kernel(const float4* __restrict__ w4,
                                   const int4*   __restrict__ s4,
                                   const int4*   __restrict__ d4,
                                   int n4) {
    int tid = blockIdx.x * blockDim.x + threadIdx.x;
    if (tid >= n4) return;
    float4 wv = w4[tid];
    int4   sv = s4[tid];
    int4   dv = d4[tid];
    atomicAdd(&g_norm[sv.x], wv.x);
    atomicAdd(&g_norm[sv.y], wv.y);
    atomicAdd(&g_norm[sv.z], wv.z);
    atomicAdd(&g_norm[sv.w], wv.w);
    atomicAdd(&g_norm[MAX_NODES + dv.x], wv.x);
    atomicAdd(&g_norm[MAX_NODES + dv.y], wv.y);
    atomicAdd(&g_norm[MAX_NODES + dv.z], wv.z);
    atomicAdd(&g_norm[MAX_NODES + dv.w], wv.w);
}

// Scalar tail for generality (launched only when E % 4 != 0).
__global__ void scatter_tail_kernel(const float* __restrict__ w,
                                    const int*   __restrict__ s,
                                    const int*   __restrict__ d,
                                    int start, int E) {
    int i = start + blockIdx.x * blockDim.x + threadIdx.x;
    if (i < E) {
        float wv = w[i];
        atomicAdd(&g_norm[s[i]], wv);
        atomicAdd(&g_norm[MAX_NODES + d[i]], wv);
    }
}

// ---------------------------------------------------------------------------
// Kernel 3: per-node rsqrt, in place, float4-vectorized over the combined
// table. deg==0 -> +inf, but such nodes never appear on the corresponding
// side of any edge, so the inf is never gathered.
// ---------------------------------------------------------------------------
__global__ void rsqrt_deg_kernel() {
    int i = blockIdx.x * blockDim.x + threadIdx.x;
    if (i < (2 * MAX_NODES) / 4) {
        float4 v = ((float4*)g_norm)[i];
        v.x = rsqrtf(v.x);
        v.y = rsqrtf(v.y);
        v.z = rsqrtf(v.z);
        v.w = rsqrtf(v.w);
        ((float4*)g_norm)[i] = v;
    }
}

// ---------------------------------------------------------------------------
// Kernel 4: per-edge gather-multiply. 4 edges per thread (this beat the
// 8-edge variant: gather is L1tex-wavefront bound, extra unroll only added
// predication overhead). Norm table (800KB) is fully L2-resident.
// ---------------------------------------------------------------------------
__global__ void gather_mul_kernel(const float4* __restrict__ w4,
                                  const int4*   __restrict__ s4,
                                  const int4*   __restrict__ d4,
                                  float4* __restrict__ out4,
                                  int n4) {
    int tid = blockIdx.x * blockDim.x + threadIdx.x;
    if (tid >= n4) return;
    float4 wv = w4[tid];
    int4   sv = s4[tid];
    int4   dv = d4[tid];
    // Front-batch all 8 random gathers for deep MLP.
    float sx = g_norm[sv.x], sy = g_norm[sv.y];
    float sz = g_norm[sv.z], sw = g_norm[sv.w];
    float dx = g_norm[MAX_NODES + dv.x], dy = g_norm[MAX_NODES + dv.y];
    float dz = g_norm[MAX_NODES + dv.z], dw = g_norm[MAX_NODES + dv.w];
    float4 r;
    r.x = sx * dx * wv.x;
    r.y = sy * dy * wv.y;
    r.z = sz * dz * wv.z;
    r.w = sw * dw * wv.w;
    out4[tid] = r;
}

// Scalar tail for generality (launched only when E % 4 != 0).
__global__ void gather_tail_kernel(const float* __restrict__ w,
                                   const int*   __restrict__ s,
                                   const int*   __restrict__ d,
                                   float* __restrict__ out,
                                   int start, int E) {
    int i = start + blockIdx.x * blockDim.x + threadIdx.x;
    if (i < E) {
        out[i] = g_norm[s[i]] * g_norm[MAX_NODES + d[i]] * w[i];
    }
}

extern "C" void kernel_launch(void* const* d_in, const int* in_sizes, int n_in,
                              void* d_out, int out_size) {
    const float* w   = (const float*)d_in[0];
    const int*   src = (const int*)d_in[1];
    const int*   dst = (const int*)d_in[2];
    float* out = (float*)d_out;

    int E    = in_sizes[0];
    int n4   = E / 4;
    int tail = E - 4 * n4;

    const int TPB = 256;
    const int NV4 = (2 * MAX_NODES) / 4;  // 100,000 float4s

    zero_deg_kernel<<<(NV4 + TPB - 1) / TPB, TPB>>>();

    scatter_deg_kernel<<<(n4 + TPB - 1) / TPB, TPB>>>(
        (const float4*)w, (const int4*)src, (const int4*)dst, n4);
    if (tail > 0) {
        scatter_tail_kernel<<<1, TPB>>>(w, src, dst, 4 * n4, E);
    }

    rsqrt_deg_kernel<<<(NV4 + TPB - 1) / TPB, TPB>>>();

    gather_mul_kernel<<<(n4 + TPB - 1) / TPB, TPB>>>(
        (const float4*)w, (const int4*)src, (const int4*)dst,
        (float4*)out, n4);
    if (tail > 0) {
        gather_tail_kernel<<<1, TPB>>>(w, src, dst, out, 4 * n4, E);
    }
}